// round 10
// baseline (speedup 1.0000x reference)
#include <cuda_runtime.h>
#include <math.h>
#include <stdint.h>

#define B_ 64
#define T_ 1024
#define D_ 256
#define H_ 512
#define O_ 256

#define GROUPS 16
#define CPG 8              // CTAs per group (column split of H)
#define BPG (B_ / GROUPS)  // 4 batches per group
#define COLS (H_ / CPG)    // 64 output columns per CTA
#define QPB 22             // quads per (CTA, batch): 64 cols = 21*3 + 1
#define QPERB (CPG * QPB)  // 176 quads per batch per group
#define TOTQ (BPG * QPERB) // 704 quads per group per step

typedef unsigned long long ull;

// Scratch (static device allocations; runtime alloc is forbidden)
__device__ float    g_xw[(size_t)B_ * T_ * H_];   // 128 MB: xW0, later reused as xW1
__device__ float    g_seq[(size_t)B_ * T_ * H_];  // 128 MB: layer-0 outputs
// Exchange quads: {h[3j],h[3j+1],h[3j+2], seq}. 16B stores/loads are single-copy
// atomic, so data+validity travel in ONE access: no fences, no acquire/release.
__device__ uint4    g_hq[2][GROUPS][BPG][QPERB];
// Monotonic per-group seq base; advanced by T_ per scan launch -> stamps are
// globally unique across launches/graph replays (stale data can never match).
__device__ unsigned g_base[GROUPS];

// ---------------------------------------------------------------------------
// Packed fp32x2 helpers (exact fp32 math, 2 FMAs per instruction)
// ---------------------------------------------------------------------------
__device__ __forceinline__ ull ffma2(ull a, ull b, ull c) {
    ull d;
    asm("fma.rn.f32x2 %0, %1, %2, %3;" : "=l"(d) : "l"(a), "l"(b), "l"(c));
    return d;
}
__device__ __forceinline__ ull addf2(ull a, ull b) {
    ull d;
    asm("add.rn.f32x2 %0, %1, %2;" : "=l"(d) : "l"(a), "l"(b));
    return d;
}
__device__ __forceinline__ ull pk2(float x, float y) {
    ull r;
    asm("mov.b64 %0, {%1, %2};" : "=l"(r) : "f"(x), "f"(y));
    return r;
}
__device__ __forceinline__ float2 unpk(ull a) {
    float2 f;
    asm("mov.b64 {%0, %1}, %2;" : "=f"(f.x), "=f"(f.y) : "l"(a));
    return f;
}

// Stamp poll: 4-byte L2 load, forced re-read (memory clobber). 4x less L2
// traffic than polling the full quad -> spin loops stay under the LTS cap.
__device__ __forceinline__ unsigned ldstamp(const unsigned* p) {
    unsigned v;
    asm volatile("ld.global.cg.u32 %0, [%1];" : "=r"(v) : "l"(p) : "memory");
    return v;
}
// One-shot data fetch (after stamp matched; quad valid by 16B atomicity)
__device__ __forceinline__ uint4 ldquad(const uint4* p) {
    uint4 v;
    asm volatile("ld.global.cg.v4.u32 {%0,%1,%2,%3}, [%4];"
                 : "=r"(v.x), "=r"(v.y), "=r"(v.z), "=r"(v.w) : "l"(p) : "memory");
    return v;
}

// ---------------------------------------------------------------------------
// tf32 tensor-core GEMM: C[M,N] = A[M,K] @ B[N,K]^T + bias1[N] + bias2[N]
// 128x128 tile, BK=32, 256 threads, warp tile 32x64 (m16n8k8). (unchanged)
// ---------------------------------------------------------------------------
__device__ __forceinline__ unsigned f2tf32(float f) {
    unsigned r;
    asm("cvt.rna.tf32.f32 %0, %1;" : "=r"(r) : "f"(f));
    return r;
}
__device__ __forceinline__ void mma_tf32(float* c, unsigned a0, unsigned a1,
                                         unsigned a2, unsigned a3,
                                         unsigned b0, unsigned b1) {
    asm volatile(
        "mma.sync.aligned.m16n8k8.row.col.f32.tf32.tf32.f32 "
        "{%0,%1,%2,%3}, {%4,%5,%6,%7}, {%8,%9}, {%0,%1,%2,%3};\n"
        : "+f"(c[0]), "+f"(c[1]), "+f"(c[2]), "+f"(c[3])
        : "r"(a0), "r"(a1), "r"(a2), "r"(a3), "r"(b0), "r"(b1));
}

__global__ void __launch_bounds__(256) gemm_tf32(
    const float* __restrict__ A, const float* __restrict__ Bm,
    const float* __restrict__ b1, const float* __restrict__ b2,
    float* __restrict__ C, int M, int N, int K)
{
    __shared__ unsigned Asm[128 * 36];
    __shared__ unsigned Bsm[128 * 36];

    const int m0 = blockIdx.y * 128;
    const int n0 = blockIdx.x * 128;
    const int tid = threadIdx.x;
    const int lane = tid & 31;
    const int wid = tid >> 5;
    const int wm = wid & 3;
    const int wn = wid >> 2;
    const int l4 = lane >> 2;
    const int lm = lane & 3;

    float acc[2][8][4];
#pragma unroll
    for (int i = 0; i < 2; i++)
#pragma unroll
        for (int j = 0; j < 8; j++)
#pragma unroll
            for (int k = 0; k < 4; k++) acc[i][j][k] = 0.f;

    for (int k0 = 0; k0 < K; k0 += 32) {
#pragma unroll
        for (int i = 0; i < 4; i++) {
            int qg = tid + 256 * i;
            int row = qg >> 3;
            int q = qg & 7;
            float4 va = *(const float4*)(A + (size_t)(m0 + row) * K + k0 + q * 4);
            unsigned* da = &Asm[row * 36 + q * 4];
            da[0] = f2tf32(va.x); da[1] = f2tf32(va.y);
            da[2] = f2tf32(va.z); da[3] = f2tf32(va.w);
            float4 vb = *(const float4*)(Bm + (size_t)(n0 + row) * K + k0 + q * 4);
            unsigned* db = &Bsm[row * 36 + q * 4];
            db[0] = f2tf32(vb.x); db[1] = f2tf32(vb.y);
            db[2] = f2tf32(vb.z); db[3] = f2tf32(vb.w);
        }
        __syncthreads();

#pragma unroll
        for (int ks = 0; ks < 4; ks++) {
            unsigned a[2][4];
#pragma unroll
            for (int mt = 0; mt < 2; mt++) {
                const unsigned* ap = &Asm[(wm * 32 + mt * 16 + l4) * 36 + ks * 8 + lm];
                a[mt][0] = ap[0];
                a[mt][1] = ap[8 * 36];
                a[mt][2] = ap[4];
                a[mt][3] = ap[8 * 36 + 4];
            }
#pragma unroll
            for (int nt = 0; nt < 8; nt++) {
                const unsigned* bp = &Bsm[(wn * 64 + nt * 8 + l4) * 36 + ks * 8 + lm];
                unsigned b0 = bp[0];
                unsigned b1v = bp[4];
                mma_tf32(acc[0][nt], a[0][0], a[0][1], a[0][2], a[0][3], b0, b1v);
                mma_tf32(acc[1][nt], a[1][0], a[1][1], a[1][2], a[1][3], b0, b1v);
            }
        }
        __syncthreads();
    }

#pragma unroll
    for (int nt = 0; nt < 8; nt++) {
        int n = n0 + wn * 64 + nt * 8 + 2 * lm;
        float bv0 = b1[n] + b2[n];
        float bv1 = b1[n + 1] + b2[n + 1];
#pragma unroll
        for (int mt = 0; mt < 2; mt++) {
            int r = m0 + wm * 32 + mt * 16 + l4;
            float2 v0 = make_float2(acc[mt][nt][0] + bv0, acc[mt][nt][1] + bv1);
            float2 v1 = make_float2(acc[mt][nt][2] + bv0, acc[mt][nt][3] + bv1);
            *(float2*)(C + (size_t)r * N + n) = v0;
            *(float2*)(C + (size_t)(r + 8) * N + n) = v1;
        }
    }
}

// ---------------------------------------------------------------------------
// Persistent recurrent scan: W in registers, seq-embedded quad exchange,
// stamp-only polling. Grid = 128 CTAs (1/SM). CTA (g,c): batches [g*4,g*4+4),
// columns [c*64,c*64+64).
// ---------------------------------------------------------------------------
template <bool STORE_SEQ, bool FUSE_FC>
__global__ void __launch_bounds__(256) scan_kernel(
    const float* __restrict__ Whh,
    const float* __restrict__ Wfc, const float* __restrict__ bfc,
    float* __restrict__ out)
{
    __shared__ __align__(16) float hb[BPG][H_];        // 8 KB: group hidden state
    __shared__ __align__(16) float part[4][BPG][COLS]; // 4 KB: k-partials
    __shared__ __align__(16) float stg[BPG][COLS];     // 1 KB: staged hn
    __shared__ unsigned sv0;

    const int tid = threadIdx.x;
    const int g = blockIdx.x >> 3;
    const int c = blockIdx.x & 7;

    const int c_loc = tid & 63;   // output column within slice
    const int kg    = tid >> 6;   // K-slice (4 x 128)
    const int ob    = tid >> 6;   // reduce mapping: batch
    const int oj    = tid & 63;   // reduce mapping: column
    const int bglob = g * BPG + ob;
    const int jglob = c * COLS + oj;

    // ---- W slice into registers (one-time; 16 CTAs share each slice via L2)
    ull w[64];
    {
        const float4* wp = (const float4*)(Whh + (size_t)(c * COLS + c_loc) * H_ + kg * 128);
#pragma unroll
        for (int i = 0; i < 32; i++) {
            float4 v = wp[i];
            w[2 * i]     = pk2(v.x, v.y);
            w[2 * i + 1] = pk2(v.z, v.w);
        }
    }

    if (tid == 0) sv0 = g_base[g];
    for (int i = tid; i < BPG * H_; i += 256) (&hb[0][0])[i] = 0.f;  // h0 = 0
    __syncthreads();
    const unsigned v0 = sv0;

    // ---- precomputed poll slots (fixed across steps): <=3 quads per thread
    int      pq_idx[3];
    float*   pq_hb[3];
    bool     pq_full[3];   // quad carries 3 valid cols (q != 21)
    bool     pq_on[3];
#pragma unroll
    for (int j = 0; j < 3; j++) {
        int idx = tid + 256 * j;
        pq_on[j] = (idx < TOTQ);
        int ii = pq_on[j] ? idx : 0;
        int b = ii / QPERB;
        int qq = ii % QPERB;
        int csrc = qq / QPB;
        int q = qq % QPB;
        pq_idx[j] = ii;
        pq_hb[j] = &hb[b][csrc * COLS + 3 * q];
        pq_full[j] = (q != QPB - 1);
    }
    const uint4* hq_base[2] = { &g_hq[0][g][0][0], &g_hq[1][g][0][0] };

    const float* xwp = g_xw + (size_t)bglob * T_ * H_ + jglob;

    for (int t = 0; t < T_; t++) {
        // stream this step's input projection early (hides DRAM latency)
        float xw_r = __ldcg(xwp + (size_t)t * H_);

        const ulonglong2* h0 = (const ulonglong2*)&hb[0][kg * 128];
        const ulonglong2* h1 = (const ulonglong2*)&hb[1][kg * 128];
        const ulonglong2* h2 = (const ulonglong2*)&hb[2][kg * 128];
        const ulonglong2* h3 = (const ulonglong2*)&hb[3][kg * 128];

        ull a0 = 0ull, b0 = 0ull, a1 = 0ull, b1 = 0ull;
        ull a2 = 0ull, b2 = 0ull, a3 = 0ull, b3 = 0ull;
#pragma unroll
        for (int q = 0; q < 32; q++) {
            ulonglong2 v0v = h0[q];   // broadcast LDS.128
            a0 = ffma2(w[2 * q], v0v.x, a0);
            b0 = ffma2(w[2 * q + 1], v0v.y, b0);
            ulonglong2 v1 = h1[q];
            a1 = ffma2(w[2 * q], v1.x, a1);
            b1 = ffma2(w[2 * q + 1], v1.y, b1);
            ulonglong2 v2 = h2[q];
            a2 = ffma2(w[2 * q], v2.x, a2);
            b2 = ffma2(w[2 * q + 1], v2.y, b2);
            ulonglong2 v3 = h3[q];
            a3 = ffma2(w[2 * q], v3.x, a3);
            b3 = ffma2(w[2 * q + 1], v3.y, b3);
        }
        float2 s0 = unpk(addf2(a0, b0));
        float2 s1 = unpk(addf2(a1, b1));
        float2 s2 = unpk(addf2(a2, b2));
        float2 s3 = unpk(addf2(a3, b3));
        part[kg][0][c_loc] = s0.x + s0.y;
        part[kg][1][c_loc] = s1.x + s1.y;
        part[kg][2][c_loc] = s2.x + s2.y;
        part[kg][3][c_loc] = s3.x + s3.y;
        __syncthreads();

        float s = part[0][ob][oj] + part[1][ob][oj] + part[2][ob][oj]
                + part[3][ob][oj] + xw_r;
        float hn = tanhf(s);

        if ((!FUSE_FC) && (t == T_ - 1)) {
            // last step, layer 0: nobody consumes h_T via exchange
            if (STORE_SEQ) __stcg(&g_seq[((size_t)bglob * T_ + t) * H_ + jglob], hn);
            break;
        }

        stg[ob][oj] = hn;
        __syncthreads();

        const int p = t & 1;
        const unsigned want = v0 + (unsigned)t + 1u;

        // ---- emit: 88 threads write this CTA's quads {3 h, seq}
        if (tid < BPG * QPB) {
            int b = tid / QPB;
            int q = tid % QPB;
            int cl = 3 * q;
            uint4 v;
            v.x = __float_as_uint(stg[b][cl]);
            v.y = __float_as_uint((cl + 1 < COLS) ? stg[b][cl + 1] : 0.f);
            v.z = __float_as_uint((cl + 2 < COLS) ? stg[b][cl + 2] : 0.f);
            v.w = want;
            __stcg((uint4*)&g_hq[p][g][b][c * QPB + q], v);
        }

        // ---- poll STAMPS only (4B loads; 4x less L2 traffic than full quads)
        {
            const uint4* base = hq_base[p];
            bool d0 = !pq_on[0], d1 = !pq_on[1], d2 = !pq_on[2];
            do {
                if (!d0) d0 = (ldstamp(&base[pq_idx[0]].w) == want);
                if (!d1) d1 = (ldstamp(&base[pq_idx[1]].w) == want);
                if (!d2) d2 = (ldstamp(&base[pq_idx[2]].w) == want);
            } while (!(d0 && d1 && d2));

            // one-shot data fetch (quads valid: 16B single-copy atomic store,
            // same-address coherence makes this read see >= the stamped write)
            uint4 r0, r1, r2;
            if (pq_on[0]) r0 = ldquad(base + pq_idx[0]);
            if (pq_on[1]) r1 = ldquad(base + pq_idx[1]);
            if (pq_on[2]) r2 = ldquad(base + pq_idx[2]);
            if (pq_on[0]) {
                pq_hb[0][0] = __uint_as_float(r0.x);
                if (pq_full[0]) { pq_hb[0][1] = __uint_as_float(r0.y);
                                  pq_hb[0][2] = __uint_as_float(r0.z); }
            }
            if (pq_on[1]) {
                pq_hb[1][0] = __uint_as_float(r1.x);
                if (pq_full[1]) { pq_hb[1][1] = __uint_as_float(r1.y);
                                  pq_hb[1][2] = __uint_as_float(r1.z); }
            }
            if (pq_on[2]) {
                pq_hb[2][0] = __uint_as_float(r2.x);
                if (pq_full[2]) { pq_hb[2][1] = __uint_as_float(r2.y);
                                  pq_hb[2][2] = __uint_as_float(r2.z); }
            }
        }

        // sequence store AFTER the poll: keeps the emit->detect window free of
        // competing store traffic (consumers read quads, never g_seq)
        if (STORE_SEQ) __stcg(&g_seq[((size_t)bglob * T_ + t) * H_ + jglob], hn);
        __syncthreads();
    }

    if (FUSE_FC) {
        // hb holds h_T for the group's 4 batches (full H).
        if (tid < 128) {
            int b = tid >> 5;
            int nl = tid & 31;
            int n = c * (O_ / CPG) + nl;
            const float4* hT = (const float4*)&hb[b][0];
            const float4* wf = (const float4*)(Wfc + (size_t)n * H_);
            float acc = 0.f;
#pragma unroll 8
            for (int k4 = 0; k4 < H_ / 4; k4++) {
                float4 a = wf[k4];
                float4 x = hT[k4];
                acc += a.x * x.x + a.y * x.y + a.z * x.z + a.w * x.w;
            }
            out[(g * BPG + b) * O_ + n] = acc + bfc[n];
        }
    }

    // advance the group's seq base for the next launch (monotonic, replay-safe)
    if (c == 0 && tid == 0) g_base[g] = v0 + (unsigned)T_;
}

// ---------------------------------------------------------------------------

extern "C" void kernel_launch(void* const* d_in, const int* in_sizes, int n_in,
                              void* d_out, int out_size)
{
    const float* x     = (const float*)d_in[0];
    const float* W_ih0 = (const float*)d_in[1];
    const float* W_hh0 = (const float*)d_in[2];
    const float* b_ih0 = (const float*)d_in[3];
    const float* b_hh0 = (const float*)d_in[4];
    const float* W_ih1 = (const float*)d_in[5];
    const float* W_hh1 = (const float*)d_in[6];
    const float* b_ih1 = (const float*)d_in[7];
    const float* b_hh1 = (const float*)d_in[8];
    const float* W_fc  = (const float*)d_in[9];
    const float* b_fc  = (const float*)d_in[10];
    float* out = (float*)d_out;

    void* p_xw = nullptr;
    void* p_seq = nullptr;
    cudaGetSymbolAddress(&p_xw, g_xw);
    cudaGetSymbolAddress(&p_seq, g_seq);

    const int MT = B_ * T_;  // 65536

    // Layer 0 input projection: g_xw = x @ W_ih0^T + b_ih0 + b_hh0
    gemm_tf32<<<dim3(H_ / 128, MT / 128), 256>>>(
        x, W_ih0, b_ih0, b_hh0, (float*)p_xw, MT, H_, D_);

    // Layer 0 scan -> g_seq
    scan_kernel<true, false><<<GROUPS * CPG, 256>>>(
        W_hh0, nullptr, nullptr, nullptr);

    // Layer 1 input projection: g_xw = g_seq @ W_ih1^T + b_ih1 + b_hh1
    gemm_tf32<<<dim3(H_ / 128, MT / 128), 256>>>(
        (const float*)p_seq, W_ih1, b_ih1, b_hh1, (float*)p_xw, MT, H_, H_);

    // Layer 1 scan + fused fc -> out
    scan_kernel<false, true><<<GROUPS * CPG, 256>>>(
        W_hh1, W_fc, b_fc, out);
}

// round 11
// speedup vs baseline: 1.0300x; 1.0300x over previous
#include <cuda_runtime.h>
#include <math.h>
#include <stdint.h>

#define B_ 64
#define T_ 1024
#define D_ 256
#define H_ 512
#define O_ 256

#define GROUPS 16
#define CPG 8              // CTAs per group (column split of H)
#define BPG (B_ / GROUPS)  // 4 batches per group
#define COLS (H_ / CPG)    // 64 output columns per CTA

typedef unsigned long long ull;

// Scratch (static device allocations; runtime alloc is forbidden)
__device__ float g_xw[(size_t)B_ * T_ * H_];   // 128 MB: xW0, later reused as xW1
__device__ float g_seq[(size_t)B_ * T_ * H_];  // 128 MB: layer-0 outputs
// Exchange pairs {float h, uint stamp} packed in 8B. Aligned 8B stores/loads
// are single-copy atomic: data + validity travel in ONE access (R8 lesson:
// detection must deliver the data; never split detect from fetch).
__device__ ull g_hp[2][GROUPS][BPG][H_];
// Monotonic per-group stamp base; advanced by T_ per scan launch -> stamps
// unique across launches/graph replays (stale data can never match).
__device__ unsigned g_base[GROUPS];

// ---------------------------------------------------------------------------
// Packed fp32x2 helpers (exact fp32 math, 2 FMAs per instruction)
// ---------------------------------------------------------------------------
__device__ __forceinline__ ull ffma2(ull a, ull b, ull c) {
    ull d;
    asm("fma.rn.f32x2 %0, %1, %2, %3;" : "=l"(d) : "l"(a), "l"(b), "l"(c));
    return d;
}
__device__ __forceinline__ ull addf2(ull a, ull b) {
    ull d;
    asm("add.rn.f32x2 %0, %1, %2;" : "=l"(d) : "l"(a), "l"(b));
    return d;
}
__device__ __forceinline__ ull pk2(float x, float y) {
    ull r;
    asm("mov.b64 %0, {%1, %2};" : "=l"(r) : "f"(x), "f"(y));
    return r;
}
__device__ __forceinline__ float2 unpk(ull a) {
    float2 f;
    asm("mov.b64 {%0, %1}, %2;" : "=f"(f.x), "=f"(f.y) : "l"(a));
    return f;
}

// Coupled poll load: one 8B access returns {h, stamp}; forced re-read.
__device__ __forceinline__ ull ldpair(const ull* p) {
    ull v;
    asm volatile("ld.global.cg.u64 %0, [%1];" : "=l"(v) : "l"(p) : "memory");
    return v;
}

// ---------------------------------------------------------------------------
// tf32 tensor-core GEMM: C[M,N] = A[M,K] @ B[N,K]^T + bias1[N] + bias2[N]
// 128x128 tile, BK=32, 256 threads, warp tile 32x64 (m16n8k8). (unchanged)
// ---------------------------------------------------------------------------
__device__ __forceinline__ unsigned f2tf32(float f) {
    unsigned r;
    asm("cvt.rna.tf32.f32 %0, %1;" : "=r"(r) : "f"(f));
    return r;
}
__device__ __forceinline__ void mma_tf32(float* c, unsigned a0, unsigned a1,
                                         unsigned a2, unsigned a3,
                                         unsigned b0, unsigned b1) {
    asm volatile(
        "mma.sync.aligned.m16n8k8.row.col.f32.tf32.tf32.f32 "
        "{%0,%1,%2,%3}, {%4,%5,%6,%7}, {%8,%9}, {%0,%1,%2,%3};\n"
        : "+f"(c[0]), "+f"(c[1]), "+f"(c[2]), "+f"(c[3])
        : "r"(a0), "r"(a1), "r"(a2), "r"(a3), "r"(b0), "r"(b1));
}

__global__ void __launch_bounds__(256) gemm_tf32(
    const float* __restrict__ A, const float* __restrict__ Bm,
    const float* __restrict__ b1, const float* __restrict__ b2,
    float* __restrict__ C, int M, int N, int K)
{
    __shared__ unsigned Asm[128 * 36];
    __shared__ unsigned Bsm[128 * 36];

    const int m0 = blockIdx.y * 128;
    const int n0 = blockIdx.x * 128;
    const int tid = threadIdx.x;
    const int lane = tid & 31;
    const int wid = tid >> 5;
    const int wm = wid & 3;
    const int wn = wid >> 2;
    const int l4 = lane >> 2;
    const int lm = lane & 3;

    float acc[2][8][4];
#pragma unroll
    for (int i = 0; i < 2; i++)
#pragma unroll
        for (int j = 0; j < 8; j++)
#pragma unroll
            for (int k = 0; k < 4; k++) acc[i][j][k] = 0.f;

    for (int k0 = 0; k0 < K; k0 += 32) {
#pragma unroll
        for (int i = 0; i < 4; i++) {
            int qg = tid + 256 * i;
            int row = qg >> 3;
            int q = qg & 7;
            float4 va = *(const float4*)(A + (size_t)(m0 + row) * K + k0 + q * 4);
            unsigned* da = &Asm[row * 36 + q * 4];
            da[0] = f2tf32(va.x); da[1] = f2tf32(va.y);
            da[2] = f2tf32(va.z); da[3] = f2tf32(va.w);
            float4 vb = *(const float4*)(Bm + (size_t)(n0 + row) * K + k0 + q * 4);
            unsigned* db = &Bsm[row * 36 + q * 4];
            db[0] = f2tf32(vb.x); db[1] = f2tf32(vb.y);
            db[2] = f2tf32(vb.z); db[3] = f2tf32(vb.w);
        }
        __syncthreads();

#pragma unroll
        for (int ks = 0; ks < 4; ks++) {
            unsigned a[2][4];
#pragma unroll
            for (int mt = 0; mt < 2; mt++) {
                const unsigned* ap = &Asm[(wm * 32 + mt * 16 + l4) * 36 + ks * 8 + lm];
                a[mt][0] = ap[0];
                a[mt][1] = ap[8 * 36];
                a[mt][2] = ap[4];
                a[mt][3] = ap[8 * 36 + 4];
            }
#pragma unroll
            for (int nt = 0; nt < 8; nt++) {
                const unsigned* bp = &Bsm[(wn * 64 + nt * 8 + l4) * 36 + ks * 8 + lm];
                unsigned b0 = bp[0];
                unsigned b1v = bp[4];
                mma_tf32(acc[0][nt], a[0][0], a[0][1], a[0][2], a[0][3], b0, b1v);
                mma_tf32(acc[1][nt], a[1][0], a[1][1], a[1][2], a[1][3], b0, b1v);
            }
        }
        __syncthreads();
    }

#pragma unroll
    for (int nt = 0; nt < 8; nt++) {
        int n = n0 + wn * 64 + nt * 8 + 2 * lm;
        float bv0 = b1[n] + b2[n];
        float bv1 = b1[n + 1] + b2[n + 1];
#pragma unroll
        for (int mt = 0; mt < 2; mt++) {
            int r = m0 + wm * 32 + mt * 16 + l4;
            float2 v0 = make_float2(acc[mt][nt][0] + bv0, acc[mt][nt][1] + bv1);
            float2 v1 = make_float2(acc[mt][nt][2] + bv0, acc[mt][nt][3] + bv1);
            *(float2*)(C + (size_t)r * N + n) = v0;
            *(float2*)(C + (size_t)(r + 8) * N + n) = v1;
        }
    }
}

// ---------------------------------------------------------------------------
// Persistent recurrent scan: warp-autonomous step.
// Grid = 128 CTAs (1/SM). CTA (g,c): batches [g*4,g*4+4), cols [c*64,c*64+64).
// Thread (warp w, lane l): col = w*8+(l&7), k-slice ks = l>>3 (128 k each),
// W row slice in 64 b64 regs. Per step, per warp (NO block sync before emit):
//   FFMA2 GEMM (4 batches) -> 2x shfl.bfly k-reduce -> lane's batch = l>>3
//   -> tanh -> emit ONE 8B {h,stamp} pair -> poll 8 fixed pairs (coupled
//   detect+data) -> unpack into hb[next] (double buffer) -> ONE syncthreads.
// ---------------------------------------------------------------------------
template <bool STORE_SEQ, bool FUSE_FC>
__global__ void __launch_bounds__(256) scan_kernel(
    const float* __restrict__ Whh,
    const float* __restrict__ Wfc, const float* __restrict__ bfc,
    float* __restrict__ out)
{
    // hb[buf][b][ks][132]: per-(b,ks) padded rows -> the 4 distinct warp LDS
    // addresses (one per ks) land on different bank groups (528B stride).
    __shared__ __align__(16) float hb[2][BPG][4][132];
    __shared__ unsigned sv0;

    const int tid = threadIdx.x;
    const int g = blockIdx.x >> 3;
    const int c = blockIdx.x & 7;

    const int w_id = tid >> 5;
    const int lane = tid & 31;
    const int colL = w_id * 8 + (lane & 7);   // column within CTA slice
    const int ks   = lane >> 3;               // k-slice 0..3 (also batch select)
    const int jglob = c * COLS + colL;
    const int gb = g * BPG + ks;              // this thread's (emit) batch

    // ---- W slice into registers: W[jglob][ks*128 .. +128) as 64 b64 k-pairs
    ull wr[64];
    {
        const float4* wp = (const float4*)(Whh + (size_t)jglob * H_ + ks * 128);
#pragma unroll
        for (int i = 0; i < 32; i++) {
            float4 v = wp[i];
            wr[2 * i]     = pk2(v.x, v.y);
            wr[2 * i + 1] = pk2(v.z, v.w);
        }
    }

    if (tid == 0) sv0 = g_base[g];
    for (int i = tid; i < 2 * BPG * 4 * 132; i += 256) (&hb[0][0][0][0])[i] = 0.f;
    __syncthreads();
    const unsigned v0 = sv0;

    // poll slots: 8 contiguous pairs starting at tid*8 (covers b*512+k space)
    const ull* pbase[2] = { &g_hp[0][g][0][0], &g_hp[1][g][0][0] };
    // unpack targets for slot j: idx = tid*8+j -> b = idx>>9, k = idx&511
    const int ub  = (tid * 8) >> 9;          // same b for all 8 (8 | 512)
    const int uk0 = (tid * 8) & 511;         // 8 consecutive k
    const int uks = uk0 >> 7;                // same ks for all 8 (8 | 128)
    const int ukk = uk0 & 127;

    const float* xwp = g_xw + (size_t)gb * T_ * H_ + jglob;
    ull* myslot[2] = { &g_hp[0][g][ks][jglob], &g_hp[1][g][ks][jglob] };

    for (int t = 0; t < T_; t++) {
        const int cur = t & 1;
        // stream this step's input projection early
        float xw_r = __ldcg(xwp + (size_t)t * H_);

        const ulonglong2* h0 = (const ulonglong2*)&hb[cur][0][ks][0];
        const ulonglong2* h1 = (const ulonglong2*)&hb[cur][1][ks][0];
        const ulonglong2* h2 = (const ulonglong2*)&hb[cur][2][ks][0];
        const ulonglong2* h3 = (const ulonglong2*)&hb[cur][3][ks][0];

        ull a0 = 0ull, b0 = 0ull, a1 = 0ull, b1 = 0ull;
        ull a2 = 0ull, b2 = 0ull, a3 = 0ull, b3 = 0ull;
#pragma unroll
        for (int q = 0; q < 32; q++) {
            ulonglong2 v0v = h0[q];
            a0 = ffma2(wr[2 * q], v0v.x, a0);
            b0 = ffma2(wr[2 * q + 1], v0v.y, b0);
            ulonglong2 v1 = h1[q];
            a1 = ffma2(wr[2 * q], v1.x, a1);
            b1 = ffma2(wr[2 * q + 1], v1.y, b1);
            ulonglong2 v2 = h2[q];
            a2 = ffma2(wr[2 * q], v2.x, a2);
            b2 = ffma2(wr[2 * q + 1], v2.y, b2);
            ulonglong2 v3 = h3[q];
            a3 = ffma2(wr[2 * q], v3.x, a3);
            b3 = ffma2(wr[2 * q + 1], v3.y, b3);
        }
        float2 u0 = unpk(addf2(a0, b0));
        float2 u1 = unpk(addf2(a1, b1));
        float2 u2 = unpk(addf2(a2, b2));
        float2 u3 = unpk(addf2(a3, b3));
        float s0 = u0.x + u0.y;
        float s1 = u1.x + u1.y;
        float s2 = u2.x + u2.y;
        float s3 = u3.x + u3.y;
        // intra-warp k-reduce across the 4 ks lanes of this column
        s0 += __shfl_xor_sync(0xffffffffu, s0, 8);
        s0 += __shfl_xor_sync(0xffffffffu, s0, 16);
        s1 += __shfl_xor_sync(0xffffffffu, s1, 8);
        s1 += __shfl_xor_sync(0xffffffffu, s1, 16);
        s2 += __shfl_xor_sync(0xffffffffu, s2, 8);
        s2 += __shfl_xor_sync(0xffffffffu, s2, 16);
        s3 += __shfl_xor_sync(0xffffffffu, s3, 8);
        s3 += __shfl_xor_sync(0xffffffffu, s3, 16);
        // this lane owns batch ks for its column
        float mine = (ks == 0) ? s0 : (ks == 1) ? s1 : (ks == 2) ? s2 : s3;
        float hn = tanhf(mine + xw_r);

        if ((!FUSE_FC) && (t == T_ - 1)) {
            // layer 0 last step: nobody consumes h_T via exchange
            if (STORE_SEQ) __stcg(&g_seq[((size_t)gb * T_ + t) * H_ + jglob], hn);
            break;
        }

        const unsigned want = v0 + (unsigned)t + 1u;

        // ---- emit: one coupled 8B {h, stamp} pair per thread, no pre-sync
        __stcg(myslot[cur], ((ull)want << 32) | (ull)__float_as_uint(hn));
        if (STORE_SEQ) __stcg(&g_seq[((size_t)gb * T_ + t) * H_ + jglob], hn);

        // ---- coupled poll: 8 fixed pairs, detect==data (MLP=8)
        ull r[8];
        {
            const ull* base = pbase[cur] + tid * 8;
            bool d0 = false, d1 = false, d2 = false, d3 = false;
            bool d4 = false, d5 = false, d6 = false, d7 = false;
            do {
                if (!d0) { r[0] = ldpair(base + 0); d0 = ((unsigned)(r[0] >> 32) == want); }
                if (!d1) { r[1] = ldpair(base + 1); d1 = ((unsigned)(r[1] >> 32) == want); }
                if (!d2) { r[2] = ldpair(base + 2); d2 = ((unsigned)(r[2] >> 32) == want); }
                if (!d3) { r[3] = ldpair(base + 3); d3 = ((unsigned)(r[3] >> 32) == want); }
                if (!d4) { r[4] = ldpair(base + 4); d4 = ((unsigned)(r[4] >> 32) == want); }
                if (!d5) { r[5] = ldpair(base + 5); d5 = ((unsigned)(r[5] >> 32) == want); }
                if (!d6) { r[6] = ldpair(base + 6); d6 = ((unsigned)(r[6] >> 32) == want); }
                if (!d7) { r[7] = ldpair(base + 7); d7 = ((unsigned)(r[7] >> 32) == want); }
            } while (!(d0 && d1 && d2 && d3 && d4 && d5 && d6 && d7));
        }
        // ---- unpack into the NEXT buffer (no race with current-step readers)
        {
            float* dst = &hb[cur ^ 1][ub][uks][ukk];
#pragma unroll
            for (int j = 0; j < 8; j++)
                dst[j] = __uint_as_float((unsigned)(r[j] & 0xffffffffull));
        }
        __syncthreads();   // the ONE block barrier per step
    }

    if (FUSE_FC) {
        // h_T lives in hb[T_&1 == 0]
        if (tid < 128) {
            int b = tid >> 5;
            int nl = tid & 31;
            int n = c * (O_ / CPG) + nl;
            const float* wf = Wfc + (size_t)n * H_;
            float acc = 0.f;
#pragma unroll 8
            for (int k4 = 0; k4 < H_ / 4; k4++) {
                float4 a = *(const float4*)(wf + k4 * 4);
                float4 x = *(const float4*)&hb[0][b][k4 >> 5][(k4 & 31) * 4];
                acc += a.x * x.x + a.y * x.y + a.z * x.z + a.w * x.w;
            }
            out[(g * BPG + b) * O_ + n] = acc + bfc[n];
        }
    }

    // advance stamp base for next launch (monotonic, replay-safe)
    if (c == 0 && tid == 0) g_base[g] = v0 + (unsigned)T_;
}

// ---------------------------------------------------------------------------

extern "C" void kernel_launch(void* const* d_in, const int* in_sizes, int n_in,
                              void* d_out, int out_size)
{
    const float* x     = (const float*)d_in[0];
    const float* W_ih0 = (const float*)d_in[1];
    const float* W_hh0 = (const float*)d_in[2];
    const float* b_ih0 = (const float*)d_in[3];
    const float* b_hh0 = (const float*)d_in[4];
    const float* W_ih1 = (const float*)d_in[5];
    const float* W_hh1 = (const float*)d_in[6];
    const float* b_ih1 = (const float*)d_in[7];
    const float* b_hh1 = (const float*)d_in[8];
    const float* W_fc  = (const float*)d_in[9];
    const float* b_fc  = (const float*)d_in[10];
    float* out = (float*)d_out;

    void* p_xw = nullptr;
    void* p_seq = nullptr;
    cudaGetSymbolAddress(&p_xw, g_xw);
    cudaGetSymbolAddress(&p_seq, g_seq);

    const int MT = B_ * T_;  // 65536

    // Layer 0 input projection: g_xw = x @ W_ih0^T + b_ih0 + b_hh0
    gemm_tf32<<<dim3(H_ / 128, MT / 128), 256>>>(
        x, W_ih0, b_ih0, b_hh0, (float*)p_xw, MT, H_, D_);

    // Layer 0 scan -> g_seq
    scan_kernel<true, false><<<GROUPS * CPG, 256>>>(
        W_hh0, nullptr, nullptr, nullptr);

    // Layer 1 input projection: g_xw = g_seq @ W_ih1^T + b_ih1 + b_hh1
    gemm_tf32<<<dim3(H_ / 128, MT / 128), 256>>>(
        (const float*)p_seq, W_ih1, b_ih1, b_hh1, (float*)p_xw, MT, H_, H_);

    // Layer 1 scan + fused fc -> out
    scan_kernel<false, true><<<GROUPS * CPG, 256>>>(
        W_hh1, W_fc, b_fc, out);
}

// round 12
// speedup vs baseline: 1.1711x; 1.1370x over previous
#include <cuda_runtime.h>
#include <math.h>
#include <stdint.h>

#define B_ 64
#define T_ 1024
#define D_ 256
#define H_ 512
#define O_ 256

#define GROUPS 16
#define CPG 8              // CTAs per group (column split of H)
#define BPG (B_ / GROUPS)  // 4 batches per group
#define COLS (H_ / CPG)    // 64 output columns per CTA

typedef unsigned long long ull;

// Scratch (static device allocations; runtime alloc is forbidden)
__device__ float g_xw[(size_t)B_ * T_ * H_];   // 128 MB: xW0, later reused as xW1
__device__ float g_seq[(size_t)B_ * T_ * H_];  // 128 MB: layer-0 outputs
// Exchange pairs {float h, uint stamp} packed in 8B. Aligned 8B stores/loads
// are single-copy atomic: data + validity travel in ONE access.
__device__ ull g_hp[2][GROUPS][BPG][H_];
// Monotonic per-group stamp base; advanced by T_ per scan launch -> stamps
// unique across launches/graph replays (stale data can never match).
__device__ unsigned g_base[GROUPS];

// ---------------------------------------------------------------------------
// Packed fp32x2 helpers (exact fp32 math, 2 FMAs per instruction)
// ---------------------------------------------------------------------------
__device__ __forceinline__ ull ffma2(ull a, ull b, ull c) {
    ull d;
    asm("fma.rn.f32x2 %0, %1, %2, %3;" : "=l"(d) : "l"(a), "l"(b), "l"(c));
    return d;
}
__device__ __forceinline__ ull addf2(ull a, ull b) {
    ull d;
    asm("add.rn.f32x2 %0, %1, %2;" : "=l"(d) : "l"(a), "l"(b));
    return d;
}
__device__ __forceinline__ ull pk2(float x, float y) {
    ull r;
    asm("mov.b64 %0, {%1, %2};" : "=l"(r) : "f"(x), "f"(y));
    return r;
}
__device__ __forceinline__ float2 unpk(ull a) {
    float2 f;
    asm("mov.b64 {%0, %1}, %2;" : "=f"(f.x), "=f"(f.y) : "l"(a));
    return f;
}

// Coupled poll load: one 8B access returns {h, stamp}; forced re-read.
__device__ __forceinline__ ull ldpair(const ull* p) {
    ull v;
    asm volatile("ld.global.cg.u64 %0, [%1];" : "=l"(v) : "l"(p) : "memory");
    return v;
}
__device__ __forceinline__ void nsleep(unsigned ns) {
    asm volatile("nanosleep.u32 %0;" :: "r"(ns));
}

// ---------------------------------------------------------------------------
// tf32 tensor-core GEMM: C[M,N] = A[M,K] @ B[N,K]^T + bias1[N] + bias2[N]
// 128x128 tile, BK=32, 256 threads, warp tile 32x64 (m16n8k8). (unchanged)
// ---------------------------------------------------------------------------
__device__ __forceinline__ unsigned f2tf32(float f) {
    unsigned r;
    asm("cvt.rna.tf32.f32 %0, %1;" : "=r"(r) : "f"(f));
    return r;
}
__device__ __forceinline__ void mma_tf32(float* c, unsigned a0, unsigned a1,
                                         unsigned a2, unsigned a3,
                                         unsigned b0, unsigned b1) {
    asm volatile(
        "mma.sync.aligned.m16n8k8.row.col.f32.tf32.tf32.f32 "
        "{%0,%1,%2,%3}, {%4,%5,%6,%7}, {%8,%9}, {%0,%1,%2,%3};\n"
        : "+f"(c[0]), "+f"(c[1]), "+f"(c[2]), "+f"(c[3])
        : "r"(a0), "r"(a1), "r"(a2), "r"(a3), "r"(b0), "r"(b1));
}

__global__ void __launch_bounds__(256) gemm_tf32(
    const float* __restrict__ A, const float* __restrict__ Bm,
    const float* __restrict__ b1, const float* __restrict__ b2,
    float* __restrict__ C, int M, int N, int K)
{
    __shared__ unsigned Asm[128 * 36];
    __shared__ unsigned Bsm[128 * 36];

    const int m0 = blockIdx.y * 128;
    const int n0 = blockIdx.x * 128;
    const int tid = threadIdx.x;
    const int lane = tid & 31;
    const int wid = tid >> 5;
    const int wm = wid & 3;
    const int wn = wid >> 2;
    const int l4 = lane >> 2;
    const int lm = lane & 3;

    float acc[2][8][4];
#pragma unroll
    for (int i = 0; i < 2; i++)
#pragma unroll
        for (int j = 0; j < 8; j++)
#pragma unroll
            for (int k = 0; k < 4; k++) acc[i][j][k] = 0.f;

    for (int k0 = 0; k0 < K; k0 += 32) {
#pragma unroll
        for (int i = 0; i < 4; i++) {
            int qg = tid + 256 * i;
            int row = qg >> 3;
            int q = qg & 7;
            float4 va = *(const float4*)(A + (size_t)(m0 + row) * K + k0 + q * 4);
            unsigned* da = &Asm[row * 36 + q * 4];
            da[0] = f2tf32(va.x); da[1] = f2tf32(va.y);
            da[2] = f2tf32(va.z); da[3] = f2tf32(va.w);
            float4 vb = *(const float4*)(Bm + (size_t)(n0 + row) * K + k0 + q * 4);
            unsigned* db = &Bsm[row * 36 + q * 4];
            db[0] = f2tf32(vb.x); db[1] = f2tf32(vb.y);
            db[2] = f2tf32(vb.z); db[3] = f2tf32(vb.w);
        }
        __syncthreads();

#pragma unroll
        for (int ks = 0; ks < 4; ks++) {
            unsigned a[2][4];
#pragma unroll
            for (int mt = 0; mt < 2; mt++) {
                const unsigned* ap = &Asm[(wm * 32 + mt * 16 + l4) * 36 + ks * 8 + lm];
                a[mt][0] = ap[0];
                a[mt][1] = ap[8 * 36];
                a[mt][2] = ap[4];
                a[mt][3] = ap[8 * 36 + 4];
            }
#pragma unroll
            for (int nt = 0; nt < 8; nt++) {
                const unsigned* bp = &Bsm[(wn * 64 + nt * 8 + l4) * 36 + ks * 8 + lm];
                unsigned b0 = bp[0];
                unsigned b1v = bp[4];
                mma_tf32(acc[0][nt], a[0][0], a[0][1], a[0][2], a[0][3], b0, b1v);
                mma_tf32(acc[1][nt], a[1][0], a[1][1], a[1][2], a[1][3], b0, b1v);
            }
        }
        __syncthreads();
    }

#pragma unroll
    for (int nt = 0; nt < 8; nt++) {
        int n = n0 + wn * 64 + nt * 8 + 2 * lm;
        float bv0 = b1[n] + b2[n];
        float bv1 = b1[n + 1] + b2[n + 1];
#pragma unroll
        for (int mt = 0; mt < 2; mt++) {
            int r = m0 + wm * 32 + mt * 16 + l4;
            float2 v0 = make_float2(acc[mt][nt][0] + bv0, acc[mt][nt][1] + bv1);
            float2 v1 = make_float2(acc[mt][nt][2] + bv0, acc[mt][nt][3] + bv1);
            *(float2*)(C + (size_t)r * N + n) = v0;
            *(float2*)(C + (size_t)(r + 8) * N + n) = v1;
        }
    }
}

// ---------------------------------------------------------------------------
// Persistent recurrent scan: warp-autonomous step, COALESCED coupled polls.
// Grid = 128 CTAs (1/SM). CTA (g,c): batches [g*4,g*4+4), cols [c*64,c*64+64).
// Thread (warp w, lane l): col = w*8+(l&7), ks = l>>3. Per step:
//   FFMA2 GEMM -> shfl.bfly k-reduce -> tanh -> emit one 8B {h,stamp} pair
//   -> poll 8 pairs at j*256+tid (warp-loads contiguous 256B, coalesced)
//   -> unpack into hb[next] -> ONE syncthreads. Nanosleep backoff on misses.
// ---------------------------------------------------------------------------
template <bool STORE_SEQ, bool FUSE_FC>
__global__ void __launch_bounds__(256) scan_kernel(
    const float* __restrict__ Whh,
    const float* __restrict__ Wfc, const float* __restrict__ bfc,
    float* __restrict__ out)
{
    // hb[buf][b][ks][132]: padded rows -> the 4 distinct warp LDS addresses
    // (one per ks) hit disjoint bank spans (528B stride).
    __shared__ __align__(16) float hb[2][BPG][4][132];
    __shared__ unsigned sv0;

    const int tid = threadIdx.x;
    const int g = blockIdx.x >> 3;
    const int c = blockIdx.x & 7;

    const int w_id = tid >> 5;
    const int lane = tid & 31;
    const int colL = w_id * 8 + (lane & 7);   // column within CTA slice
    const int ks   = lane >> 3;               // k-slice 0..3 (also batch select)
    const int jglob = c * COLS + colL;
    const int gb = g * BPG + ks;              // this thread's (emit) batch

    // ---- W slice into registers: W[jglob][ks*128 .. +128) as 64 b64 k-pairs
    ull wr[64];
    {
        const float4* wp = (const float4*)(Whh + (size_t)jglob * H_ + ks * 128);
#pragma unroll
        for (int i = 0; i < 32; i++) {
            float4 v = wp[i];
            wr[2 * i]     = pk2(v.x, v.y);
            wr[2 * i + 1] = pk2(v.z, v.w);
        }
    }

    if (tid == 0) sv0 = g_base[g];
    for (int i = tid; i < 2 * BPG * 4 * 132; i += 256) (&hb[0][0][0][0])[i] = 0.f;
    __syncthreads();
    const unsigned v0 = sv0;

    const ull* pbase[2] = { &g_hp[0][g][0][0], &g_hp[1][g][0][0] };
    const float* xwp = g_xw + (size_t)gb * T_ * H_ + jglob;
    ull* myslot[2] = { &g_hp[0][g][ks][jglob], &g_hp[1][g][ks][jglob] };

    for (int t = 0; t < T_; t++) {
        const int cur = t & 1;
        // stream this step's input projection early
        float xw_r = __ldcg(xwp + (size_t)t * H_);

        const ulonglong2* h0 = (const ulonglong2*)&hb[cur][0][ks][0];
        const ulonglong2* h1 = (const ulonglong2*)&hb[cur][1][ks][0];
        const ulonglong2* h2 = (const ulonglong2*)&hb[cur][2][ks][0];
        const ulonglong2* h3 = (const ulonglong2*)&hb[cur][3][ks][0];

        ull a0 = 0ull, b0 = 0ull, a1 = 0ull, b1 = 0ull;
        ull a2 = 0ull, b2 = 0ull, a3 = 0ull, b3 = 0ull;
#pragma unroll
        for (int q = 0; q < 32; q++) {
            ulonglong2 v0v = h0[q];
            a0 = ffma2(wr[2 * q], v0v.x, a0);
            b0 = ffma2(wr[2 * q + 1], v0v.y, b0);
            ulonglong2 v1 = h1[q];
            a1 = ffma2(wr[2 * q], v1.x, a1);
            b1 = ffma2(wr[2 * q + 1], v1.y, b1);
            ulonglong2 v2 = h2[q];
            a2 = ffma2(wr[2 * q], v2.x, a2);
            b2 = ffma2(wr[2 * q + 1], v2.y, b2);
            ulonglong2 v3 = h3[q];
            a3 = ffma2(wr[2 * q], v3.x, a3);
            b3 = ffma2(wr[2 * q + 1], v3.y, b3);
        }
        float2 u0 = unpk(addf2(a0, b0));
        float2 u1 = unpk(addf2(a1, b1));
        float2 u2 = unpk(addf2(a2, b2));
        float2 u3 = unpk(addf2(a3, b3));
        float s0 = u0.x + u0.y;
        float s1 = u1.x + u1.y;
        float s2 = u2.x + u2.y;
        float s3 = u3.x + u3.y;
        // intra-warp k-reduce across the 4 ks lanes of this column
        s0 += __shfl_xor_sync(0xffffffffu, s0, 8);
        s0 += __shfl_xor_sync(0xffffffffu, s0, 16);
        s1 += __shfl_xor_sync(0xffffffffu, s1, 8);
        s1 += __shfl_xor_sync(0xffffffffu, s1, 16);
        s2 += __shfl_xor_sync(0xffffffffu, s2, 8);
        s2 += __shfl_xor_sync(0xffffffffu, s2, 16);
        s3 += __shfl_xor_sync(0xffffffffu, s3, 8);
        s3 += __shfl_xor_sync(0xffffffffu, s3, 16);
        // this lane owns batch ks for its column
        float mine = (ks == 0) ? s0 : (ks == 1) ? s1 : (ks == 2) ? s2 : s3;
        float hn = tanhf(mine + xw_r);

        if ((!FUSE_FC) && (t == T_ - 1)) {
            // layer 0 last step: nobody consumes h_T via exchange
            if (STORE_SEQ) __stcg(&g_seq[((size_t)gb * T_ + t) * H_ + jglob], hn);
            break;
        }

        const unsigned want = v0 + (unsigned)t + 1u;

        // ---- emit: one coupled 8B {h, stamp} pair per thread, no pre-sync
        __stcg(myslot[cur], ((ull)want << 32) | (ull)__float_as_uint(hn));
        if (STORE_SEQ) __stcg(&g_seq[((size_t)gb * T_ + t) * H_ + jglob], hn);

        // ---- coupled poll: slots j*256+tid -> each warp-load is a contiguous
        // 256B block (coalesced, 2 lines). Nanosleep backoff between passes.
        ull r[8];
        {
            const ull* base = pbase[cur];
            bool done[8];
#pragma unroll
            for (int j = 0; j < 8; j++) done[j] = false;
            int remaining = 8;
            for (;;) {
#pragma unroll
                for (int j = 0; j < 8; j++) {
                    if (!done[j]) {
                        r[j] = ldpair(base + j * 256 + tid);
                        if ((unsigned)(r[j] >> 32) == want) {
                            done[j] = true;
                            remaining--;
                        }
                    }
                }
                if (remaining == 0) break;
                nsleep(200);
            }
        }
        // ---- unpack into the NEXT buffer (no race with current-step readers)
#pragma unroll
        for (int j = 0; j < 8; j++) {
            int idx = j * 256 + tid;     // = b*512 + k
            int b = idx >> 9;
            int k = idx & 511;
            hb[cur ^ 1][b][k >> 7][k & 127] =
                __uint_as_float((unsigned)(r[j] & 0xffffffffull));
        }
        __syncthreads();   // the ONE block barrier per step
    }

    if (FUSE_FC) {
        // h_T lives in hb[0]  (last unpack wrote cur^1 with cur = (T_-1)&1 = 1)
        if (tid < 128) {
            int b = tid >> 5;
            int nl = tid & 31;
            int n = c * (O_ / CPG) + nl;
            const float* wf = Wfc + (size_t)n * H_;
            float acc = 0.f;
#pragma unroll 8
            for (int k4 = 0; k4 < H_ / 4; k4++) {
                float4 a = *(const float4*)(wf + k4 * 4);
                float4 x = *(const float4*)&hb[0][b][k4 >> 5][(k4 & 31) * 4];
                acc += a.x * x.x + a.y * x.y + a.z * x.z + a.w * x.w;
            }
            out[(g * BPG + b) * O_ + n] = acc + bfc[n];
        }
    }

    // advance stamp base for next launch (monotonic, replay-safe)
    if (c == 0 && tid == 0) g_base[g] = v0 + (unsigned)T_;
}

// ---------------------------------------------------------------------------

extern "C" void kernel_launch(void* const* d_in, const int* in_sizes, int n_in,
                              void* d_out, int out_size)
{
    const float* x     = (const float*)d_in[0];
    const float* W_ih0 = (const float*)d_in[1];
    const float* W_hh0 = (const float*)d_in[2];
    const float* b_ih0 = (const float*)d_in[3];
    const float* b_hh0 = (const float*)d_in[4];
    const float* W_ih1 = (const float*)d_in[5];
    const float* W_hh1 = (const float*)d_in[6];
    const float* b_ih1 = (const float*)d_in[7];
    const float* b_hh1 = (const float*)d_in[8];
    const float* W_fc  = (const float*)d_in[9];
    const float* b_fc  = (const float*)d_in[10];
    float* out = (float*)d_out;

    void* p_xw = nullptr;
    void* p_seq = nullptr;
    cudaGetSymbolAddress(&p_xw, g_xw);
    cudaGetSymbolAddress(&p_seq, g_seq);

    const int MT = B_ * T_;  // 65536

    // Layer 0 input projection: g_xw = x @ W_ih0^T + b_ih0 + b_hh0
    gemm_tf32<<<dim3(H_ / 128, MT / 128), 256>>>(
        x, W_ih0, b_ih0, b_hh0, (float*)p_xw, MT, H_, D_);

    // Layer 0 scan -> g_seq
    scan_kernel<true, false><<<GROUPS * CPG, 256>>>(
        W_hh0, nullptr, nullptr, nullptr);

    // Layer 1 input projection: g_xw = g_seq @ W_ih1^T + b_ih1 + b_hh1
    gemm_tf32<<<dim3(H_ / 128, MT / 128), 256>>>(
        (const float*)p_seq, W_ih1, b_ih1, b_hh1, (float*)p_xw, MT, H_, H_);

    // Layer 1 scan + fused fc -> out
    scan_kernel<false, true><<<GROUPS * CPG, 256>>>(
        W_hh1, W_fc, b_fc, out);
}

// round 13
// speedup vs baseline: 1.2251x; 1.0461x over previous
#include <cuda_runtime.h>
#include <math.h>
#include <stdint.h>

#define B_ 64
#define T_ 1024
#define D_ 256
#define H_ 512
#define O_ 256

#define GROUPS 16
#define CPG 8              // CTAs per group (column split of H)
#define BPG (B_ / GROUPS)  // 4 batches per group
#define COLS (H_ / CPG)    // 64 output columns per CTA

typedef unsigned long long ull;

// Scratch (static device allocations; runtime alloc is forbidden)
__device__ float g_xw[(size_t)B_ * T_ * H_];   // 128 MB: xW0, later reused as xW1
__device__ float g_seq[(size_t)B_ * T_ * H_];  // 128 MB: layer-0 outputs
// Exchange pairs {float h, uint stamp} packed in 8B (single-copy atomic:
// data + validity in ONE access). Double-buffered by timestep parity.
__device__ ull g_hp[2][GROUPS][BPG][H_];
// Monotonic per-group stamp base; advanced by T_ per scan launch.
__device__ unsigned g_base[GROUPS];

// ---------------------------------------------------------------------------
// Packed fp32x2 helpers (exact fp32 math, 2 FMAs per instruction)
// ---------------------------------------------------------------------------
__device__ __forceinline__ ull ffma2(ull a, ull b, ull c) {
    ull d;
    asm("fma.rn.f32x2 %0, %1, %2, %3;" : "=l"(d) : "l"(a), "l"(b), "l"(c));
    return d;
}
__device__ __forceinline__ ull addf2(ull a, ull b) {
    ull d;
    asm("add.rn.f32x2 %0, %1, %2;" : "=l"(d) : "l"(a), "l"(b));
    return d;
}
__device__ __forceinline__ ull pk2(float x, float y) {
    ull r;
    asm("mov.b64 %0, {%1, %2};" : "=l"(r) : "f"(x), "f"(y));
    return r;
}
__device__ __forceinline__ float2 unpk(ull a) {
    float2 f;
    asm("mov.b64 {%0, %1}, %2;" : "=f"(f.x), "=f"(f.y) : "l"(a));
    return f;
}
__device__ __forceinline__ ull ldpair(const ull* p) {
    ull v;
    asm volatile("ld.global.cg.u64 %0, [%1];" : "=l"(v) : "l"(p) : "memory");
    return v;
}
__device__ __forceinline__ void nsleep(unsigned ns) {
    asm volatile("nanosleep.u32 %0;" :: "r"(ns));
}

// ---------------------------------------------------------------------------
// tf32 tensor-core GEMM: C[M,N] = A[M,K] @ B[N,K]^T + bias1[N] + bias2[N]
// (unchanged from R12 — GEMMs total ~140us, not the bottleneck)
// ---------------------------------------------------------------------------
__device__ __forceinline__ unsigned f2tf32(float f) {
    unsigned r;
    asm("cvt.rna.tf32.f32 %0, %1;" : "=r"(r) : "f"(f));
    return r;
}
__device__ __forceinline__ void mma_tf32(float* c, unsigned a0, unsigned a1,
                                         unsigned a2, unsigned a3,
                                         unsigned b0, unsigned b1) {
    asm volatile(
        "mma.sync.aligned.m16n8k8.row.col.f32.tf32.tf32.f32 "
        "{%0,%1,%2,%3}, {%4,%5,%6,%7}, {%8,%9}, {%0,%1,%2,%3};\n"
        : "+f"(c[0]), "+f"(c[1]), "+f"(c[2]), "+f"(c[3])
        : "r"(a0), "r"(a1), "r"(a2), "r"(a3), "r"(b0), "r"(b1));
}

__global__ void __launch_bounds__(256) gemm_tf32(
    const float* __restrict__ A, const float* __restrict__ Bm,
    const float* __restrict__ b1, const float* __restrict__ b2,
    float* __restrict__ C, int M, int N, int K)
{
    __shared__ unsigned Asm[128 * 36];
    __shared__ unsigned Bsm[128 * 36];

    const int m0 = blockIdx.y * 128;
    const int n0 = blockIdx.x * 128;
    const int tid = threadIdx.x;
    const int lane = tid & 31;
    const int wid = tid >> 5;
    const int wm = wid & 3;
    const int wn = wid >> 2;
    const int l4 = lane >> 2;
    const int lm = lane & 3;

    float acc[2][8][4];
#pragma unroll
    for (int i = 0; i < 2; i++)
#pragma unroll
        for (int j = 0; j < 8; j++)
#pragma unroll
            for (int k = 0; k < 4; k++) acc[i][j][k] = 0.f;

    for (int k0 = 0; k0 < K; k0 += 32) {
#pragma unroll
        for (int i = 0; i < 4; i++) {
            int qg = tid + 256 * i;
            int row = qg >> 3;
            int q = qg & 7;
            float4 va = *(const float4*)(A + (size_t)(m0 + row) * K + k0 + q * 4);
            unsigned* da = &Asm[row * 36 + q * 4];
            da[0] = f2tf32(va.x); da[1] = f2tf32(va.y);
            da[2] = f2tf32(va.z); da[3] = f2tf32(va.w);
            float4 vb = *(const float4*)(Bm + (size_t)(n0 + row) * K + k0 + q * 4);
            unsigned* db = &Bsm[row * 36 + q * 4];
            db[0] = f2tf32(vb.x); db[1] = f2tf32(vb.y);
            db[2] = f2tf32(vb.z); db[3] = f2tf32(vb.w);
        }
        __syncthreads();

#pragma unroll
        for (int ks = 0; ks < 4; ks++) {
            unsigned a[2][4];
#pragma unroll
            for (int mt = 0; mt < 2; mt++) {
                const unsigned* ap = &Asm[(wm * 32 + mt * 16 + l4) * 36 + ks * 8 + lm];
                a[mt][0] = ap[0];
                a[mt][1] = ap[8 * 36];
                a[mt][2] = ap[4];
                a[mt][3] = ap[8 * 36 + 4];
            }
#pragma unroll
            for (int nt = 0; nt < 8; nt++) {
                const unsigned* bp = &Bsm[(wn * 64 + nt * 8 + l4) * 36 + ks * 8 + lm];
                unsigned b0 = bp[0];
                unsigned b1v = bp[4];
                mma_tf32(acc[0][nt], a[0][0], a[0][1], a[0][2], a[0][3], b0, b1v);
                mma_tf32(acc[1][nt], a[1][0], a[1][1], a[1][2], a[1][3], b0, b1v);
            }
        }
        __syncthreads();
    }

#pragma unroll
    for (int nt = 0; nt < 8; nt++) {
        int n = n0 + wn * 64 + nt * 8 + 2 * lm;
        float bv0 = b1[n] + b2[n];
        float bv1 = b1[n + 1] + b2[n + 1];
#pragma unroll
        for (int mt = 0; mt < 2; mt++) {
            int r = m0 + wm * 32 + mt * 16 + l4;
            float2 v0 = make_float2(acc[mt][nt][0] + bv0, acc[mt][nt][1] + bv1);
            float2 v1 = make_float2(acc[mt][nt][2] + bv0, acc[mt][nt][3] + bv1);
            *(float2*)(C + (size_t)r * N + n) = v0;
            *(float2*)(C + (size_t)(r + 8) * N + n) = v1;
        }
    }
}

// ---------------------------------------------------------------------------
// Persistent recurrent scan: BATCH-ROTATED pipeline.
// Batches are independent recurrences; slot b advances batch b one timestep.
// A batch's exchange (emit -> L2 -> peers' poll) has ~3 slots of other
// batches' compute to complete -> the L2 RTT leaves the critical path.
// Per slot: resolve prefetched polls (2 pairs) -> unpack -> 1 bar ->
// prefetch next slot's polls -> 64 FFMA2 -> 2 shfl reduce -> tanh -> emit.
// ---------------------------------------------------------------------------
template <bool STORE_SEQ, bool FUSE_FC>
__global__ void __launch_bounds__(256) scan_kernel(
    const float* __restrict__ Whh,
    const float* __restrict__ Wfc, const float* __restrict__ bfc,
    float* __restrict__ out)
{
    // hb[par][b][ks][132]: 528B row stride -> the 4 ks broadcast-groups of a
    // warp read 4 distinct banks (16B apart mod 128) -> conflict-free.
    __shared__ __align__(16) float hb[2][BPG][4][132];
    __shared__ unsigned sv0;

    const int tid = threadIdx.x;
    const int g = blockIdx.x >> 3;
    const int c = blockIdx.x & 7;

    const int w_id = tid >> 5;
    const int lane = tid & 31;
    const int colL = w_id * 8 + (lane & 7);   // column within CTA slice
    const int ks   = lane >> 3;               // k-slice 0..3 (128 k each)
    const int jglob = c * COLS + colL;
    const bool emitter = (lane < 8);          // lanes 0-7 own the final sums

    // ---- W slice into registers: W[jglob][ks*128 .. +128) as 64 b64 k-pairs
    ull wr[64];
    {
        const float4* wp = (const float4*)(Whh + (size_t)jglob * H_ + ks * 128);
#pragma unroll
        for (int i = 0; i < 32; i++) {
            float4 v = wp[i];
            wr[2 * i]     = pk2(v.x, v.y);
            wr[2 * i + 1] = pk2(v.z, v.w);
        }
    }

    if (tid == 0) sv0 = g_base[g];
    for (int i = tid; i < 2 * BPG * 4 * 132; i += 256) (&hb[0][0][0][0])[i] = 0.f;

    // xw pipeline: load t=0 now (lands before first use)
    float xw_cur[4], xw_nxt[4];
#pragma unroll
    for (int b = 0; b < BPG; b++) xw_nxt[b] = 0.f;
    if (emitter) {
#pragma unroll
        for (int b = 0; b < BPG; b++)
            xw_nxt[b] = __ldcg(&g_xw[(size_t)(g * BPG + b) * T_ * H_ + jglob]);
    }
    __syncthreads();
    const unsigned v0 = sv0;

    ull pr0 = 0, pr1 = 0;           // inflight poll results for the next slot
    const ull* pa = &g_hp[0][g][0][tid];

    for (int t = 0; t < T_; t++) {
        const int dpar = (t + 1) & 1;          // parity of data h(t-1)
        const unsigned want = v0 + (unsigned)t; // stamp of h(t-1)

        // rotate xw pipeline; issue loads for t+1 (consumed next superstep)
#pragma unroll
        for (int b = 0; b < BPG; b++) xw_cur[b] = xw_nxt[b];
        if (emitter && (t + 1 < T_)) {
#pragma unroll
            for (int b = 0; b < BPG; b++)
                xw_nxt[b] = __ldcg(&g_xw[((size_t)(g * BPG + b) * T_ + (t + 1)) * H_ + jglob]);
        }

#pragma unroll
        for (int b = 0; b < BPG; b++) {
            if (t > 0) {
                // resolve the prefetched polls for (b, t-1)
                bool d0 = ((unsigned)(pr0 >> 32) == want);
                bool d1 = ((unsigned)(pr1 >> 32) == want);
                while (!(d0 && d1)) {
                    if (!d0) { pr0 = ldpair(pa);       d0 = ((unsigned)(pr0 >> 32) == want); }
                    if (!d1) { pr1 = ldpair(pa + 256); d1 = ((unsigned)(pr1 >> 32) == want); }
                    if (!(d0 && d1)) nsleep(40);
                }
                hb[dpar][b][tid >> 7][tid & 127] =
                    __uint_as_float((unsigned)(pr0 & 0xffffffffull));
                hb[dpar][b][(tid >> 7) + 2][tid & 127] =
                    __uint_as_float((unsigned)(pr1 & 0xffffffffull));
                __syncthreads();
            }

            // prefetch polls for the next slot (data parity: (nt-1)&1)
            {
                int nb = (b + 1) & 3;
                int pq = (b == 3) ? (t & 1) : dpar;
                pa = &g_hp[pq][g][nb][tid];
                pr0 = ldpair(pa);
                pr1 = ldpair(pa + 256);
            }

            // GEMM: batch b, this thread's 128-k slice (W in regs, h broadcast LDS)
            const ulonglong2* hp = (const ulonglong2*)&hb[dpar][b][ks][0];
            ull A = 0ull, Bc = 0ull;
#pragma unroll
            for (int q = 0; q < 32; q++) {
                ulonglong2 v = hp[q];
                A  = ffma2(wr[2 * q],     v.x, A);
                Bc = ffma2(wr[2 * q + 1], v.y, Bc);
            }
            float2 u = unpk(addf2(A, Bc));
            float s = u.x + u.y;
            s += __shfl_xor_sync(0xffffffffu, s, 8);
            s += __shfl_xor_sync(0xffffffffu, s, 16);

            if (emitter) {
                float hn = tanhf(s + xw_cur[b]);
                if ((t < T_ - 1) || FUSE_FC)
                    __stcg(&g_hp[t & 1][g][b][jglob],
                           ((ull)(want + 1u) << 32) | (ull)__float_as_uint(hn));
                if (STORE_SEQ)
                    __stcg(&g_seq[((size_t)(g * BPG + b) * T_ + t) * H_ + jglob], hn);
            }
        }
    }

    if (FUSE_FC) {
        __syncthreads();   // last slot's FFMA reads of hb[0] complete before reuse
        const unsigned wantT = v0 + (unsigned)T_;
        const int qp = (T_ - 1) & 1;
#pragma unroll
        for (int b = 0; b < BPG; b++) {
            const ull* a = &g_hp[qp][g][b][tid];
            ull r0 = ldpair(a), r1 = ldpair(a + 256);
            bool d0 = ((unsigned)(r0 >> 32) == wantT);
            bool d1 = ((unsigned)(r1 >> 32) == wantT);
            while (!(d0 && d1)) {
                if (!d0) { r0 = ldpair(a);       d0 = ((unsigned)(r0 >> 32) == wantT); }
                if (!d1) { r1 = ldpair(a + 256); d1 = ((unsigned)(r1 >> 32) == wantT); }
                if (!(d0 && d1)) nsleep(40);
            }
            hb[0][b][tid >> 7][tid & 127] =
                __uint_as_float((unsigned)(r0 & 0xffffffffull));
            hb[0][b][(tid >> 7) + 2][tid & 127] =
                __uint_as_float((unsigned)(r1 & 0xffffffffull));
        }
        __syncthreads();
        if (tid < 128) {
            int b = tid >> 5;
            int nl = tid & 31;
            int n = c * (O_ / CPG) + nl;
            const float* wf = Wfc + (size_t)n * H_;
            float acc = 0.f;
#pragma unroll 8
            for (int k4 = 0; k4 < H_ / 4; k4++) {
                float4 a = *(const float4*)(wf + k4 * 4);
                float4 x = *(const float4*)&hb[0][b][k4 >> 5][(k4 & 31) * 4];
                acc += a.x * x.x + a.y * x.y + a.z * x.z + a.w * x.w;
            }
            out[(g * BPG + b) * O_ + n] = acc + bfc[n];
        }
    }

    // advance stamp base for next launch (monotonic, replay-safe)
    if (c == 0 && tid == 0) g_base[g] = v0 + (unsigned)T_;
}

// ---------------------------------------------------------------------------

extern "C" void kernel_launch(void* const* d_in, const int* in_sizes, int n_in,
                              void* d_out, int out_size)
{
    const float* x     = (const float*)d_in[0];
    const float* W_ih0 = (const float*)d_in[1];
    const float* W_hh0 = (const float*)d_in[2];
    const float* b_ih0 = (const float*)d_in[3];
    const float* b_hh0 = (const float*)d_in[4];
    const float* W_ih1 = (const float*)d_in[5];
    const float* W_hh1 = (const float*)d_in[6];
    const float* b_ih1 = (const float*)d_in[7];
    const float* b_hh1 = (const float*)d_in[8];
    const float* W_fc  = (const float*)d_in[9];
    const float* b_fc  = (const float*)d_in[10];
    float* out = (float*)d_out;

    void* p_xw = nullptr;
    void* p_seq = nullptr;
    cudaGetSymbolAddress(&p_xw, g_xw);
    cudaGetSymbolAddress(&p_seq, g_seq);

    const int MT = B_ * T_;  // 65536

    // Layer 0 input projection: g_xw = x @ W_ih0^T + b_ih0 + b_hh0
    gemm_tf32<<<dim3(H_ / 128, MT / 128), 256>>>(
        x, W_ih0, b_ih0, b_hh0, (float*)p_xw, MT, H_, D_);

    // Layer 0 scan -> g_seq
    scan_kernel<true, false><<<GROUPS * CPG, 256>>>(
        W_hh0, nullptr, nullptr, nullptr);

    // Layer 1 input projection: g_xw = g_seq @ W_ih1^T + b_ih1 + b_hh1
    gemm_tf32<<<dim3(H_ / 128, MT / 128), 256>>>(
        (const float*)p_seq, W_ih1, b_ih1, b_hh1, (float*)p_xw, MT, H_, H_);

    // Layer 1 scan + fused fc -> out
    scan_kernel<false, true><<<GROUPS * CPG, 256>>>(
        W_hh1, W_fc, b_fc, out);
}

// round 14
// speedup vs baseline: 1.2398x; 1.0120x over previous
#include <cuda_runtime.h>
#include <math.h>
#include <stdint.h>

#define B_ 64
#define T_ 1024
#define D_ 256
#define H_ 512
#define O_ 256

#define GROUPS 16
#define CPG 8              // CTAs per group (column split of H)
#define BPG (B_ / GROUPS)  // 4 batches per group
#define COLS (H_ / CPG)    // 64 output columns per CTA

typedef unsigned long long ull;

// Scratch (static device allocations; runtime alloc is forbidden)
__device__ float g_xw[(size_t)B_ * T_ * H_];   // 128 MB: xW0, later reused as xW1
__device__ float g_seq[(size_t)B_ * T_ * H_];  // 128 MB: layer-0 outputs
// Exchange pairs {float h, uint stamp} packed in 8B (single-copy atomic:
// data + validity in ONE access). Double-buffered by timestep parity.
__device__ ull g_hp[2][GROUPS][BPG][H_];
// Monotonic per-group stamp base; advanced by T_ per scan launch.
__device__ unsigned g_base[GROUPS];

// ---------------------------------------------------------------------------
// Packed fp32x2 helpers (exact fp32 math, 2 FMAs per instruction)
// ---------------------------------------------------------------------------
__device__ __forceinline__ ull ffma2(ull a, ull b, ull c) {
    ull d;
    asm("fma.rn.f32x2 %0, %1, %2, %3;" : "=l"(d) : "l"(a), "l"(b), "l"(c));
    return d;
}
__device__ __forceinline__ ull addf2(ull a, ull b) {
    ull d;
    asm("add.rn.f32x2 %0, %1, %2;" : "=l"(d) : "l"(a), "l"(b));
    return d;
}
__device__ __forceinline__ ull pk2(float x, float y) {
    ull r;
    asm("mov.b64 %0, {%1, %2};" : "=l"(r) : "f"(x), "f"(y));
    return r;
}
__device__ __forceinline__ float2 unpk(ull a) {
    float2 f;
    asm("mov.b64 {%0, %1}, %2;" : "=f"(f.x), "=f"(f.y) : "l"(a));
    return f;
}
__device__ __forceinline__ ull ldpair(const ull* p) {
    ull v;
    asm volatile("ld.global.cg.u64 %0, [%1];" : "=l"(v) : "l"(p) : "memory");
    return v;
}
__device__ __forceinline__ void nsleep(unsigned ns) {
    asm volatile("nanosleep.u32 %0;" :: "r"(ns));
}

// ---------------------------------------------------------------------------
// tf32 tensor-core GEMM: C[M,N] = A[M,K] @ B[N,K]^T + bias1[N] + bias2[N]
// (unchanged — not the bottleneck)
// ---------------------------------------------------------------------------
__device__ __forceinline__ unsigned f2tf32(float f) {
    unsigned r;
    asm("cvt.rna.tf32.f32 %0, %1;" : "=r"(r) : "f"(f));
    return r;
}
__device__ __forceinline__ void mma_tf32(float* c, unsigned a0, unsigned a1,
                                         unsigned a2, unsigned a3,
                                         unsigned b0, unsigned b1) {
    asm volatile(
        "mma.sync.aligned.m16n8k8.row.col.f32.tf32.tf32.f32 "
        "{%0,%1,%2,%3}, {%4,%5,%6,%7}, {%8,%9}, {%0,%1,%2,%3};\n"
        : "+f"(c[0]), "+f"(c[1]), "+f"(c[2]), "+f"(c[3])
        : "r"(a0), "r"(a1), "r"(a2), "r"(a3), "r"(b0), "r"(b1));
}

__global__ void __launch_bounds__(256) gemm_tf32(
    const float* __restrict__ A, const float* __restrict__ Bm,
    const float* __restrict__ b1, const float* __restrict__ b2,
    float* __restrict__ C, int M, int N, int K)
{
    __shared__ unsigned Asm[128 * 36];
    __shared__ unsigned Bsm[128 * 36];

    const int m0 = blockIdx.y * 128;
    const int n0 = blockIdx.x * 128;
    const int tid = threadIdx.x;
    const int lane = tid & 31;
    const int wid = tid >> 5;
    const int wm = wid & 3;
    const int wn = wid >> 2;
    const int l4 = lane >> 2;
    const int lm = lane & 3;

    float acc[2][8][4];
#pragma unroll
    for (int i = 0; i < 2; i++)
#pragma unroll
        for (int j = 0; j < 8; j++)
#pragma unroll
            for (int k = 0; k < 4; k++) acc[i][j][k] = 0.f;

    for (int k0 = 0; k0 < K; k0 += 32) {
#pragma unroll
        for (int i = 0; i < 4; i++) {
            int qg = tid + 256 * i;
            int row = qg >> 3;
            int q = qg & 7;
            float4 va = *(const float4*)(A + (size_t)(m0 + row) * K + k0 + q * 4);
            unsigned* da = &Asm[row * 36 + q * 4];
            da[0] = f2tf32(va.x); da[1] = f2tf32(va.y);
            da[2] = f2tf32(va.z); da[3] = f2tf32(va.w);
            float4 vb = *(const float4*)(Bm + (size_t)(n0 + row) * K + k0 + q * 4);
            unsigned* db = &Bsm[row * 36 + q * 4];
            db[0] = f2tf32(vb.x); db[1] = f2tf32(vb.y);
            db[2] = f2tf32(vb.z); db[3] = f2tf32(vb.w);
        }
        __syncthreads();

#pragma unroll
        for (int ks = 0; ks < 4; ks++) {
            unsigned a[2][4];
#pragma unroll
            for (int mt = 0; mt < 2; mt++) {
                const unsigned* ap = &Asm[(wm * 32 + mt * 16 + l4) * 36 + ks * 8 + lm];
                a[mt][0] = ap[0];
                a[mt][1] = ap[8 * 36];
                a[mt][2] = ap[4];
                a[mt][3] = ap[8 * 36 + 4];
            }
#pragma unroll
            for (int nt = 0; nt < 8; nt++) {
                const unsigned* bp = &Bsm[(wn * 64 + nt * 8 + l4) * 36 + ks * 8 + lm];
                unsigned b0 = bp[0];
                unsigned b1v = bp[4];
                mma_tf32(acc[0][nt], a[0][0], a[0][1], a[0][2], a[0][3], b0, b1v);
                mma_tf32(acc[1][nt], a[1][0], a[1][1], a[1][2], a[1][3], b0, b1v);
            }
        }
        __syncthreads();
    }

#pragma unroll
    for (int nt = 0; nt < 8; nt++) {
        int n = n0 + wn * 64 + nt * 8 + 2 * lm;
        float bv0 = b1[n] + b2[n];
        float bv1 = b1[n + 1] + b2[n + 1];
#pragma unroll
        for (int mt = 0; mt < 2; mt++) {
            int r = m0 + wm * 32 + mt * 16 + l4;
            float2 v0 = make_float2(acc[mt][nt][0] + bv0, acc[mt][nt][1] + bv1);
            float2 v1 = make_float2(acc[mt][nt][2] + bv0, acc[mt][nt][3] + bv1);
            *(float2*)(C + (size_t)r * N + n) = v0;
            *(float2*)(C + (size_t)(r + 8) * N + n) = v1;
        }
    }
}

// ---------------------------------------------------------------------------
// Persistent recurrent scan: BATCH-ROTATED pipeline, pair-wise resolve.
// Per superstep t (advances all 4 batches one step):
//   pair bp in {0,2}:
//     resolve prefetched polls for batches bp,bp+1 (h(t-1)) -> unpack to hb
//       (+ consumer-side coalesced g_seq stores: the resolve data IS the
//        sequence output, already in [b][k]-coalesced form)
//     ONE syncthreads -> prefetch next pair -> GEMM+emit bp -> GEMM+emit bp+1
// 2 barriers/superstep (was 4); emits stay off the g_seq store path.
// ---------------------------------------------------------------------------
template <bool STORE_SEQ, bool FUSE_FC>
__global__ void __launch_bounds__(256) scan_kernel(
    const float* __restrict__ Whh,
    const float* __restrict__ Wfc, const float* __restrict__ bfc,
    float* __restrict__ out)
{
    // hb[par][b][ks][132]: 528B row stride -> conflict-free broadcast LDS.
    __shared__ __align__(16) float hb[2][BPG][4][132];
    __shared__ unsigned sv0;

    const int tid = threadIdx.x;
    const int g = blockIdx.x >> 3;
    const int c = blockIdx.x & 7;

    const int w_id = tid >> 5;
    const int lane = tid & 31;
    const int colL = w_id * 8 + (lane & 7);   // column within CTA slice
    const int ks   = lane >> 3;               // k-slice 0..3 (128 k each)
    const int jglob = c * COLS + colL;
    const bool emitter = (lane < 8);          // lanes 0-7 own the final sums

    // ---- W slice into registers: W[jglob][ks*128 .. +128) as 64 b64 k-pairs
    ull wr[64];
    {
        const float4* wp = (const float4*)(Whh + (size_t)jglob * H_ + ks * 128);
#pragma unroll
        for (int i = 0; i < 32; i++) {
            float4 v = wp[i];
            wr[2 * i]     = pk2(v.x, v.y);
            wr[2 * i + 1] = pk2(v.z, v.w);
        }
    }

    if (tid == 0) sv0 = g_base[g];
    for (int i = tid; i < 2 * BPG * 4 * 132; i += 256) (&hb[0][0][0][0])[i] = 0.f;

    // xw pipeline: load t=0 now
    float xw_cur[4], xw_nxt[4];
#pragma unroll
    for (int b = 0; b < BPG; b++) xw_nxt[b] = 0.f;
    if (emitter) {
#pragma unroll
        for (int b = 0; b < BPG; b++)
            xw_nxt[b] = __ldcg(&g_xw[(size_t)(g * BPG + b) * T_ * H_ + jglob]);
    }
    __syncthreads();
    const unsigned v0 = sv0;

    // inflight polls for the next PAIR: pr[0..1] batch nb, pr[2..3] batch nb+1
    ull pr[4] = {0, 0, 0, 0};
    const ull* pa0 = &g_hp[0][g][0][tid];
    const ull* pa1 = &g_hp[0][g][1][tid];

    for (int t = 0; t < T_; t++) {
        const int dpar = (t + 1) & 1;           // parity holding h(t-1)
        const unsigned want = v0 + (unsigned)t; // stamp of h(t-1)

        // rotate xw pipeline; issue loads for t+1
#pragma unroll
        for (int b = 0; b < BPG; b++) xw_cur[b] = xw_nxt[b];
        if (emitter && (t + 1 < T_)) {
#pragma unroll
            for (int b = 0; b < BPG; b++)
                xw_nxt[b] = __ldcg(&g_xw[((size_t)(g * BPG + b) * T_ + (t + 1)) * H_ + jglob]);
        }

#pragma unroll
        for (int bp = 0; bp < BPG; bp += 2) {
            if (t > 0) {
                // resolve prefetched polls for batches bp, bp+1 at h(t-1)
                bool d0 = ((unsigned)(pr[0] >> 32) == want);
                bool d1 = ((unsigned)(pr[1] >> 32) == want);
                bool d2 = ((unsigned)(pr[2] >> 32) == want);
                bool d3 = ((unsigned)(pr[3] >> 32) == want);
                while (!(d0 && d1 && d2 && d3)) {
                    if (!d0) { pr[0] = ldpair(pa0);       d0 = ((unsigned)(pr[0] >> 32) == want); }
                    if (!d1) { pr[1] = ldpair(pa0 + 256); d1 = ((unsigned)(pr[1] >> 32) == want); }
                    if (!d2) { pr[2] = ldpair(pa1);       d2 = ((unsigned)(pr[2] >> 32) == want); }
                    if (!d3) { pr[3] = ldpair(pa1 + 256); d3 = ((unsigned)(pr[3] >> 32) == want); }
                    if (!(d0 && d1 && d2 && d3)) nsleep(40);
                }
                float f0 = __uint_as_float((unsigned)(pr[0] & 0xffffffffull));
                float f1 = __uint_as_float((unsigned)(pr[1] & 0xffffffffull));
                float f2 = __uint_as_float((unsigned)(pr[2] & 0xffffffffull));
                float f3 = __uint_as_float((unsigned)(pr[3] & 0xffffffffull));
                hb[dpar][bp][tid >> 7][tid & 127] = f0;
                hb[dpar][bp][(tid >> 7) + 2][tid & 127] = f1;
                hb[dpar][bp + 1][tid >> 7][tid & 127] = f2;
                hb[dpar][bp + 1][(tid >> 7) + 2][tid & 127] = f3;
                if (STORE_SEQ) {
                    // consumer-side sequence store: resolve data IS seq[t-1],
                    // already coalesced over tid. Off the emit path.
                    float* s0 = &g_seq[((size_t)(g * BPG + bp) * T_ + (t - 1)) * H_];
                    float* s1 = &g_seq[((size_t)(g * BPG + bp + 1) * T_ + (t - 1)) * H_];
                    __stcg(s0 + tid, f0);
                    __stcg(s0 + tid + 256, f1);
                    __stcg(s1 + tid, f2);
                    __stcg(s1 + tid + 256, f3);
                }
                __syncthreads();
            }

            // prefetch polls for the next pair
            {
                int nb, pq;
                if (bp == 0) { nb = 2; pq = dpar; }      // pair (t, 2)
                else         { nb = 0; pq = t & 1; }     // pair (t+1, 0)
                pa0 = &g_hp[pq][g][nb][tid];
                pa1 = &g_hp[pq][g][nb + 1][tid];
                pr[0] = ldpair(pa0);
                pr[1] = ldpair(pa0 + 256);
                pr[2] = ldpair(pa1);
                pr[3] = ldpair(pa1 + 256);
            }

            // GEMM + emit for the two batches of this pair
#pragma unroll
            for (int u = 0; u < 2; u++) {
                const int b = bp + u;
                const ulonglong2* hp = (const ulonglong2*)&hb[dpar][b][ks][0];
                ull A = 0ull, Bc = 0ull;
#pragma unroll
                for (int q = 0; q < 32; q++) {
                    ulonglong2 v = hp[q];
                    A  = ffma2(wr[2 * q],     v.x, A);
                    Bc = ffma2(wr[2 * q + 1], v.y, Bc);
                }
                float2 uu = unpk(addf2(A, Bc));
                float s = uu.x + uu.y;
                s += __shfl_xor_sync(0xffffffffu, s, 8);
                s += __shfl_xor_sync(0xffffffffu, s, 16);

                if (emitter) {
                    float hn = tanhf(s + xw_cur[b]);
                    if ((t < T_ - 1) || FUSE_FC) {
                        __stcg(&g_hp[t & 1][g][b][jglob],
                               ((ull)(want + 1u) << 32) | (ull)__float_as_uint(hn));
                    } else if (STORE_SEQ) {
                        // t = T-1 in scan0: never exchanged; store directly once
                        __stcg(&g_seq[((size_t)(g * BPG + b) * T_ + t) * H_ + jglob], hn);
                    }
                }
            }
        }
    }

    if (FUSE_FC) {
        __syncthreads();   // last GEMM reads of hb[0] complete before reuse
        const unsigned wantT = v0 + (unsigned)T_;
        const int qp = (T_ - 1) & 1;
#pragma unroll
        for (int b = 0; b < BPG; b++) {
            const ull* a = &g_hp[qp][g][b][tid];
            ull r0 = ldpair(a), r1 = ldpair(a + 256);
            bool d0 = ((unsigned)(r0 >> 32) == wantT);
            bool d1 = ((unsigned)(r1 >> 32) == wantT);
            while (!(d0 && d1)) {
                if (!d0) { r0 = ldpair(a);       d0 = ((unsigned)(r0 >> 32) == wantT); }
                if (!d1) { r1 = ldpair(a + 256); d1 = ((unsigned)(r1 >> 32) == wantT); }
                if (!(d0 && d1)) nsleep(40);
            }
            hb[0][b][tid >> 7][tid & 127] =
                __uint_as_float((unsigned)(r0 & 0xffffffffull));
            hb[0][b][(tid >> 7) + 2][tid & 127] =
                __uint_as_float((unsigned)(r1 & 0xffffffffull));
        }
        __syncthreads();
        if (tid < 128) {
            int b = tid >> 5;
            int nl = tid & 31;
            int n = c * (O_ / CPG) + nl;
            const float* wf = Wfc + (size_t)n * H_;
            float acc = 0.f;
#pragma unroll 8
            for (int k4 = 0; k4 < H_ / 4; k4++) {
                float4 a = *(const float4*)(wf + k4 * 4);
                float4 x = *(const float4*)&hb[0][b][k4 >> 5][(k4 & 31) * 4];
                acc += a.x * x.x + a.y * x.y + a.z * x.z + a.w * x.w;
            }
            out[(g * BPG + b) * O_ + n] = acc + bfc[n];
        }
    }

    // advance stamp base for next launch (monotonic, replay-safe)
    if (c == 0 && tid == 0) g_base[g] = v0 + (unsigned)T_;
}

// ---------------------------------------------------------------------------

extern "C" void kernel_launch(void* const* d_in, const int* in_sizes, int n_in,
                              void* d_out, int out_size)
{
    const float* x     = (const float*)d_in[0];
    const float* W_ih0 = (const float*)d_in[1];
    const float* W_hh0 = (const float*)d_in[2];
    const float* b_ih0 = (const float*)d_in[3];
    const float* b_hh0 = (const float*)d_in[4];
    const float* W_ih1 = (const float*)d_in[5];
    const float* W_hh1 = (const float*)d_in[6];
    const float* b_ih1 = (const float*)d_in[7];
    const float* b_hh1 = (const float*)d_in[8];
    const float* W_fc  = (const float*)d_in[9];
    const float* b_fc  = (const float*)d_in[10];
    float* out = (float*)d_out;

    void* p_xw = nullptr;
    void* p_seq = nullptr;
    cudaGetSymbolAddress(&p_xw, g_xw);
    cudaGetSymbolAddress(&p_seq, g_seq);

    const int MT = B_ * T_;  // 65536

    // Layer 0 input projection: g_xw = x @ W_ih0^T + b_ih0 + b_hh0
    gemm_tf32<<<dim3(H_ / 128, MT / 128), 256>>>(
        x, W_ih0, b_ih0, b_hh0, (float*)p_xw, MT, H_, D_);

    // Layer 0 scan -> g_seq
    scan_kernel<true, false><<<GROUPS * CPG, 256>>>(
        W_hh0, nullptr, nullptr, nullptr);

    // Layer 1 input projection: g_xw = g_seq @ W_ih1^T + b_ih1 + b_hh1
    gemm_tf32<<<dim3(H_ / 128, MT / 128), 256>>>(
        (const float*)p_seq, W_ih1, b_ih1, b_hh1, (float*)p_xw, MT, H_, H_);

    // Layer 1 scan + fused fc -> out
    scan_kernel<false, true><<<GROUPS * CPG, 256>>>(
        W_hh1, W_fc, b_fc, out);
}